// round 4
// baseline (speedup 1.0000x reference)
#include <cuda_runtime.h>
#include <cuda_bf16.h>
#include <math.h>
#include <cstdint>

// ContactMapHead via HMMA (mma.sync bf16) split-GEMMs (tcgen05 rejected by
// sm_103 PTX target). Split fp32 -> (hi,lo) bf16;
//   C = A_hi*B_hi + A_hi*B_lo + A_lo*B_hi (fp32 accum).
// R4: phase-fused mainloop — per native-K chunk load A_hi/A_lo/B_hi/B_lo once,
// issue all 3 phase MMA sets from the same ldmatrix fragments.

#define B_    4
#define S_    2048
#define D_    1024
#define P_    256
#define MROWS 8192

#define BK    32            // native K elems per chunk
#define ROWB  80            // padded smem row bytes (64 data + 16 pad)

// stage bytes: 2 A-tiles (32*MT rows) + 2 B-tiles (128 rows)
#define STAGEB(MT)  ((2 * 32 * (MT) + 256) * ROWB)
#define SMEMB(MT)   (2 * STAGEB(MT))

// ---------------- scratch ----------------
__device__ unsigned short g_hs_hi[(size_t)MROWS * D_];
__device__ unsigned short g_hs_lo[(size_t)MROWS * D_];
__device__ unsigned short g_w_hi[(size_t)P_ * D_];
__device__ unsigned short g_w_lo[(size_t)P_ * D_];
__device__ unsigned short g_h_hi[(size_t)MROWS * P_];
__device__ unsigned short g_h_lo[(size_t)MROWS * P_];

// ---------------- asm helpers ----------------
__device__ __forceinline__ uint32_t smem_u32(const void* p) {
    uint32_t a;
    asm("{ .reg .u64 t; cvta.to.shared.u64 t, %1; cvt.u32.u64 %0, t; }" : "=r"(a) : "l"(p));
    return a;
}
__device__ __forceinline__ void cpa16(uint32_t s, const void* g) {
    asm volatile("cp.async.cg.shared.global [%0], [%1], 16;" :: "r"(s), "l"(g));
}
#define CP_COMMIT() asm volatile("cp.async.commit_group;" ::: "memory")
#define CP_WAIT1()  asm volatile("cp.async.wait_group 1;" ::: "memory")
#define CP_WAIT0()  asm volatile("cp.async.wait_group 0;" ::: "memory")

#define LDMX4(r, addr) \
    asm volatile("ldmatrix.sync.aligned.m8n8.x4.shared.b16 {%0,%1,%2,%3}, [%4];" \
        : "=r"((r)[0]), "=r"((r)[1]), "=r"((r)[2]), "=r"((r)[3]) : "r"(addr))

#define MMA16816(d, a, b0, b1) \
    asm volatile("mma.sync.aligned.m16n8k16.row.col.f32.bf16.bf16.f32 " \
        "{%0,%1,%2,%3},{%4,%5,%6,%7},{%8,%9},{%0,%1,%2,%3};" \
        : "+f"((d)[0]), "+f"((d)[1]), "+f"((d)[2]), "+f"((d)[3]) \
        : "r"((a)[0]), "r"((a)[1]), "r"((a)[2]), "r"((a)[3]), "r"(b0), "r"(b1))

// ---------------- fp32 -> (hi,lo) bf16 ----------------
__global__ __launch_bounds__(256) void convert_kernel(
    const float* __restrict__ src, unsigned short* __restrict__ hi,
    unsigned short* __restrict__ lo, int n4)
{
    int i = blockIdx.x * 256 + threadIdx.x;
    if (i >= n4) return;
    float4 v = ((const float4*)src)[i];
    ushort4 h, l;
    float f; __nv_bfloat16 b;
    b = __float2bfloat16(v.x); h.x = *(unsigned short*)&b; f = v.x - __bfloat162float(b);
    b = __float2bfloat16(f);   l.x = *(unsigned short*)&b;
    b = __float2bfloat16(v.y); h.y = *(unsigned short*)&b; f = v.y - __bfloat162float(b);
    b = __float2bfloat16(f);   l.y = *(unsigned short*)&b;
    b = __float2bfloat16(v.z); h.z = *(unsigned short*)&b; f = v.z - __bfloat162float(b);
    b = __float2bfloat16(f);   l.z = *(unsigned short*)&b;
    b = __float2bfloat16(v.w); h.w = *(unsigned short*)&b; f = v.w - __bfloat162float(b);
    b = __float2bfloat16(f);   l.w = *(unsigned short*)&b;
    ((ushort4*)hi)[i] = h;
    ((ushort4*)lo)[i] = l;
}

// ---------------- GEMM machinery ----------------
struct GemmSrc {
    const unsigned short *ahi, *alo, *bhi, *blo;
    int K;
};

// Load one chunk: A_hi/A_lo (32*MT rows x 32) + B_hi/B_lo (128 rows x 32)
template<int MT>
__device__ __forceinline__ void load_chunk(
    uint32_t sbase, int slot, const GemmSrc& g, int koff,
    int arow0, int brow0, int tid)
{
    const int AROWS = 32 * MT;
    uint32_t st   = sbase + slot * STAGEB(MT);
    uint32_t sAhi = st;
    uint32_t sAlo = st + AROWS * ROWB;
    uint32_t sBhi = st + 2 * AROWS * ROWB;
    uint32_t sBlo = sBhi + 128 * ROWB;
#pragma unroll
    for (int i = 0; i < (AROWS * 4) / 256; i++) {
        int ch = tid + i * 256;
        int row = ch >> 2, c16 = ch & 3;
        size_t go = (size_t)(arow0 + row) * g.K + koff + c16 * 8;
        uint32_t so = row * ROWB + c16 * 16;
        cpa16(sAhi + so, g.ahi + go);
        cpa16(sAlo + so, g.alo + go);
    }
#pragma unroll
    for (int i = 0; i < 2; i++) {
        int ch = tid + i * 256;
        int row = ch >> 2, c16 = ch & 3;
        size_t go = (size_t)(brow0 + row) * g.K + koff + c16 * 8;
        uint32_t so = row * ROWB + c16 * 16;
        cpa16(sBhi + so, g.bhi + go);
        cpa16(sBlo + so, g.blo + go);
    }
}

// CTA tile: (64*MT/2? -> 32*MT rows) x 128 cols. 8 warps: 2 (M) x 4 (N),
// warp tile (16*MT) x 32. Double-buffered cp.async pipeline.
template<int MT>
__device__ __forceinline__ void gemm_main(
    uint32_t sbase, const GemmSrc& g, int NC, int arow0, int brow0,
    float (&acc)[MT][4][4])
{
    const int tid = threadIdx.x, lane = tid & 31, w = tid >> 5;
    const int wm = w & 1, wn = w >> 1;
    const int AROWS = 32 * MT;

    load_chunk<MT>(sbase, 0, g, 0, arow0, brow0, tid);
    CP_COMMIT();

    const uint32_t aoff = (wm * (16 * MT) + (lane & 15)) * ROWB + (lane >> 4) * 16;
    const uint32_t boff = (wn * 32 + (lane & 15)) * ROWB + (lane >> 4) * 16;

    for (int c = 0; c < NC; c++) {
        if (c + 1 < NC) {
            load_chunk<MT>(sbase, (c + 1) & 1, g, (c + 1) * BK, arow0, brow0, tid);
            CP_COMMIT();
            CP_WAIT1();
        } else {
            CP_WAIT0();
        }
        __syncthreads();

        uint32_t st   = sbase + (c & 1) * STAGEB(MT);
        uint32_t sAhi = st;
        uint32_t sAlo = st + AROWS * ROWB;
        uint32_t sBhi = st + 2 * AROWS * ROWB;
        uint32_t sBlo = sBhi + 128 * ROWB;

#pragma unroll
        for (int k16 = 0; k16 < 2; k16++) {
            uint32_t ahi[MT][4], alo[MT][4], bhi[2][4], blo[2][4];
#pragma unroll
            for (int mt = 0; mt < MT; mt++) {
                LDMX4(ahi[mt], sAhi + aoff + mt * 16 * ROWB + k16 * 32);
                LDMX4(alo[mt], sAlo + aoff + mt * 16 * ROWB + k16 * 32);
            }
#pragma unroll
            for (int np = 0; np < 2; np++) {
                LDMX4(bhi[np], sBhi + boff + np * 16 * ROWB + k16 * 32);
                LDMX4(blo[np], sBlo + boff + np * 16 * ROWB + k16 * 32);
            }
#pragma unroll
            for (int mt = 0; mt < MT; mt++)
#pragma unroll
                for (int nt = 0; nt < 4; nt++) {
                    uint32_t bh0 = bhi[nt >> 1][nt & 1], bh1 = bhi[nt >> 1][(nt & 1) + 2];
                    uint32_t bl0 = blo[nt >> 1][nt & 1], bl1 = blo[nt >> 1][(nt & 1) + 2];
                    MMA16816(acc[mt][nt], ahi[mt], bh0, bh1);   // hi*hi
                    MMA16816(acc[mt][nt], ahi[mt], bl0, bl1);   // hi*lo
                    MMA16816(acc[mt][nt], alo[mt], bh0, bh1);   // lo*hi
                }
        }
        __syncthreads();   // all warps done with this stage before it is reloaded
    }
}

// ---------------- proj: h = relu(hs@W^T + b) -> hi/lo bf16 (MT=2, 64x128) ----
__global__ __launch_bounds__(256) void proj_gemm_kernel(const float* __restrict__ bias)
{
    extern __shared__ char smem[];
    uint32_t sbase = smem_u32(smem);
    float acc[2][4][4] = {};

    GemmSrc g;
    g.ahi = g_hs_hi; g.alo = g_hs_lo; g.bhi = g_w_hi; g.blo = g_w_lo;
    g.K = D_;

    const int row0 = blockIdx.y * 64, col0 = blockIdx.x * 128;
    gemm_main<2>(sbase, g, D_ / BK, row0, col0, acc);

    const int lane = threadIdx.x & 31, w = threadIdx.x >> 5;
    const int wm = w & 1, wn = w >> 1;
    uint32_t* hhi = (uint32_t*)g_h_hi;
    uint32_t* hlo = (uint32_t*)g_h_lo;

#pragma unroll
    for (int nt = 0; nt < 4; nt++) {
        int col = col0 + wn * 32 + nt * 8 + (lane & 3) * 2;
        float b0 = bias[col], b1 = bias[col + 1];
#pragma unroll
        for (int mt = 0; mt < 2; mt++) {
            int r0 = row0 + wm * 32 + mt * 16 + (lane >> 2);
#pragma unroll
            for (int hh = 0; hh < 2; hh++) {
                int r = r0 + hh * 8;
                float v0 = fmaxf(acc[mt][nt][hh * 2 + 0] + b0, 0.f);
                float v1 = fmaxf(acc[mt][nt][hh * 2 + 1] + b1, 0.f);
                __nv_bfloat16 h0 = __float2bfloat16(v0), h1 = __float2bfloat16(v1);
                float l0f = v0 - __bfloat162float(h0);
                float l1f = v1 - __bfloat162float(h1);
                __nv_bfloat16 l0 = __float2bfloat16(l0f), l1 = __float2bfloat16(l1f);
                uint32_t hp = (uint32_t)*(unsigned short*)&h0 | ((uint32_t)*(unsigned short*)&h1 << 16);
                uint32_t lp = (uint32_t)*(unsigned short*)&l0 | ((uint32_t)*(unsigned short*)&l1 << 16);
                size_t o = ((size_t)r * P_ + col) >> 1;
                hhi[o] = hp;
                hlo[o] = lp;
            }
        }
    }
}

// ---------------- scores: out = (h@h^T)*s + c (MT=4, 128x128, tri+mirror) ----
__global__ __launch_bounds__(256) void scores_gemm_kernel(
    const float* __restrict__ clf_w, const float* __restrict__ clf_b,
    float* __restrict__ out)
{
    extern __shared__ char smem[];
    uint32_t sbase = smem_u32(smem);

    const int idx = blockIdx.x;
    int bi = (int)((sqrtf(8.f * (float)idx + 1.f) - 1.f) * 0.5f);
    while ((bi + 1) * (bi + 2) / 2 <= idx) bi++;
    while (bi * (bi + 1) / 2 > idx)       bi--;
    const int bj = idx - bi * (bi + 1) / 2;
    const int rows0 = bi * 128, cols0 = bj * 128;

    const size_t hoff = (size_t)blockIdx.z * S_ * P_;
    float* outb = out + (size_t)blockIdx.z * S_ * S_;

    float acc[4][4][4] = {};
    GemmSrc g;
    g.ahi = g_h_hi + hoff; g.alo = g_h_lo + hoff;
    g.bhi = g_h_hi + hoff; g.blo = g_h_lo + hoff;
    g.K = P_;
    gemm_main<4>(sbase, g, P_ / BK, rows0, cols0, acc);

    const float sw = clf_w[0], cb = clf_b[0];
    const int lane = threadIdx.x & 31, w = threadIdx.x >> 5;
    const int wm = w & 1, wn = w >> 1;
    float* sep = (float*)smem;   // [128][132] fp32 = 67584 <= 81920

    __syncthreads();
#pragma unroll
    for (int mt = 0; mt < 4; mt++)
#pragma unroll
        for (int nt = 0; nt < 4; nt++) {
            int lr = wm * 64 + mt * 16 + (lane >> 2);
            int lc = wn * 32 + nt * 8 + (lane & 3) * 2;
            sep[lr * 132 + lc]           = acc[mt][nt][0];
            sep[lr * 132 + lc + 1]       = acc[mt][nt][1];
            sep[(lr + 8) * 132 + lc]     = acc[mt][nt][2];
            sep[(lr + 8) * 132 + lc + 1] = acc[mt][nt][3];
        }
    __syncthreads();

    // direct block (coalesced rows)
#pragma unroll
    for (int pass = 0; pass < 16; pass++) {
        int r = pass * 8 + w;
        float4 v = *(const float4*)(sep + r * 132 + lane * 4);
        v.x = fmaf(v.x, sw, cb); v.y = fmaf(v.y, sw, cb);
        v.z = fmaf(v.z, sw, cb); v.w = fmaf(v.w, sw, cb);
        *(float4*)&outb[(size_t)(rows0 + r) * S_ + cols0 + lane * 4] = v;
    }
    // mirrored block
    if (bi != bj) {
#pragma unroll
        for (int pass = 0; pass < 16; pass++) {
            int c = pass * 8 + w;
            float4 v;
            v.x = fmaf(sep[(lane * 4 + 0) * 132 + c], sw, cb);
            v.y = fmaf(sep[(lane * 4 + 1) * 132 + c], sw, cb);
            v.z = fmaf(sep[(lane * 4 + 2) * 132 + c], sw, cb);
            v.w = fmaf(sep[(lane * 4 + 3) * 132 + c], sw, cb);
            *(float4*)&outb[(size_t)(cols0 + c) * S_ + rows0 + lane * 4] = v;
        }
    }
}

// ---------------- launch ----------------
extern "C" void kernel_launch(void* const* d_in, const int* in_sizes, int n_in,
                              void* d_out, int out_size)
{
    const float* hs     = (const float*)d_in[0];
    const float* proj_w = (const float*)d_in[1];
    const float* proj_b = (const float*)d_in[2];
    const float* clf_w  = (const float*)d_in[3];
    const float* clf_b  = (const float*)d_in[4];
    float* out = (float*)d_out;

    unsigned short *hs_hi, *hs_lo, *w_hi, *w_lo;
    cudaGetSymbolAddress((void**)&hs_hi, g_hs_hi);
    cudaGetSymbolAddress((void**)&hs_lo, g_hs_lo);
    cudaGetSymbolAddress((void**)&w_hi,  g_w_hi);
    cudaGetSymbolAddress((void**)&w_lo,  g_w_lo);

    cudaFuncSetAttribute(proj_gemm_kernel,
                         cudaFuncAttributeMaxDynamicSharedMemorySize, SMEMB(2));
    cudaFuncSetAttribute(scores_gemm_kernel,
                         cudaFuncAttributeMaxDynamicSharedMemorySize, SMEMB(4));

    {   // fp32 -> hi/lo bf16
        int n4 = (MROWS * D_) / 4;
        convert_kernel<<<(n4 + 255) / 256, 256>>>(hs, hs_hi, hs_lo, n4);
        int w4 = (P_ * D_) / 4;
        convert_kernel<<<(w4 + 255) / 256, 256>>>(proj_w, w_hi, w_lo, w4);
    }
    {   // projection + relu + resplit: 64x128 tiles
        dim3 grid(P_ / 128, MROWS / 64);    // (2, 128)
        proj_gemm_kernel<<<grid, 256, SMEMB(2)>>>(proj_b);
    }
    {   // symmetric scores: 128x128 triangular tiles
        const int nt = S_ / 128;                 // 16
        dim3 grid(nt * (nt + 1) / 2, 1, B_);     // (136, 1, 4)
        scores_gemm_kernel<<<grid, 256, SMEMB(4)>>>(clf_w, clf_b, out);
    }
}

// round 5
// speedup vs baseline: 1.7071x; 1.7071x over previous
#include <cuda_runtime.h>
#include <cuda_bf16.h>
#include <math.h>
#include <cstdint>

// ContactMapHead via HMMA (mma.sync bf16) GEMMs (tcgen05 rejected by sm_103 target).
// proj: 3-phase split bf16 (hi*hi + hi*lo + lo*hi) for accurate h.
// scores: pure bf16 on h_hi (error ~3e-4 << 1e-3 gate) — 3x less work.
// Structure is the validated R3 mainloop (4-stage cp.async, 1 phase per chunk).

#define B_    4
#define S_    2048
#define D_    1024
#define P_    256
#define MROWS 8192

#define BK      32
#define STAGES  4
#define ROWB    80                         // 64 data bytes + 16 pad

#define STAGEB(MT)  ((32 * (MT) + 128) * ROWB)   // A rows + 128 B rows
#define SMEMB(MT)   (STAGES * STAGEB(MT))

// ---------------- scratch ----------------
__device__ unsigned short g_hs_hi[(size_t)MROWS * D_];
__device__ unsigned short g_hs_lo[(size_t)MROWS * D_];
__device__ unsigned short g_w_hi[(size_t)P_ * D_];
__device__ unsigned short g_w_lo[(size_t)P_ * D_];
__device__ unsigned short g_h_hi[(size_t)MROWS * P_];

// ---------------- asm helpers ----------------
__device__ __forceinline__ uint32_t smem_u32(const void* p) {
    uint32_t a;
    asm("{ .reg .u64 t; cvta.to.shared.u64 t, %1; cvt.u32.u64 %0, t; }" : "=r"(a) : "l"(p));
    return a;
}
__device__ __forceinline__ void cpa16(uint32_t s, const void* g) {
    asm volatile("cp.async.cg.shared.global [%0], [%1], 16;" :: "r"(s), "l"(g));
}
#define CP_COMMIT() asm volatile("cp.async.commit_group;" ::: "memory")
#define CP_WAIT2()  asm volatile("cp.async.wait_group 2;" ::: "memory")

#define LDMX4(r, addr) \
    asm volatile("ldmatrix.sync.aligned.m8n8.x4.shared.b16 {%0,%1,%2,%3}, [%4];" \
        : "=r"((r)[0]), "=r"((r)[1]), "=r"((r)[2]), "=r"((r)[3]) : "r"(addr))

#define MMA16816(d, a, b0, b1) \
    asm volatile("mma.sync.aligned.m16n8k16.row.col.f32.bf16.bf16.f32 " \
        "{%0,%1,%2,%3},{%4,%5,%6,%7},{%8,%9},{%0,%1,%2,%3};" \
        : "+f"((d)[0]), "+f"((d)[1]), "+f"((d)[2]), "+f"((d)[3]) \
        : "r"((a)[0]), "r"((a)[1]), "r"((a)[2]), "r"((a)[3]), "r"(b0), "r"(b1))

// ---------------- fp32 -> (hi,lo) bf16 ----------------
__global__ __launch_bounds__(256) void convert_kernel(
    const float* __restrict__ src, unsigned short* __restrict__ hi,
    unsigned short* __restrict__ lo, int n4)
{
    int i = blockIdx.x * 256 + threadIdx.x;
    if (i >= n4) return;
    float4 v = ((const float4*)src)[i];
    ushort4 h, l;
    float f; __nv_bfloat16 b;
    b = __float2bfloat16(v.x); h.x = *(unsigned short*)&b; f = v.x - __bfloat162float(b);
    b = __float2bfloat16(f);   l.x = *(unsigned short*)&b;
    b = __float2bfloat16(v.y); h.y = *(unsigned short*)&b; f = v.y - __bfloat162float(b);
    b = __float2bfloat16(f);   l.y = *(unsigned short*)&b;
    b = __float2bfloat16(v.z); h.z = *(unsigned short*)&b; f = v.z - __bfloat162float(b);
    b = __float2bfloat16(f);   l.z = *(unsigned short*)&b;
    b = __float2bfloat16(v.w); h.w = *(unsigned short*)&b; f = v.w - __bfloat162float(b);
    b = __float2bfloat16(f);   l.w = *(unsigned short*)&b;
    ((ushort4*)hi)[i] = h;
    ((ushort4*)lo)[i] = l;
}

// ---------------- GEMM machinery (R3-style: 1 phase per chunk) ----------------
struct GemmSrc {
    const unsigned short *ahi, *alo, *bhi, *blo;
    int K, cpp;   // native K, chunks per phase
};

template<int MT>
__device__ __forceinline__ void load_chunk(
    uint32_t sbase, int slot, const GemmSrc& g, int c,
    int arow0, int brow0, int tid)
{
    const int AROWS = 32 * MT;
    int p   = c / g.cpp;
    int off = (c - p * g.cpp) * BK;
    const unsigned short* A = (p < 2)  ? g.ahi : g.alo;
    const unsigned short* B = (p == 1) ? g.blo : g.bhi;
    uint32_t sA = sbase + slot * STAGEB(MT);
    uint32_t sB = sA + AROWS * ROWB;
#pragma unroll
    for (int i = 0; i < (AROWS * 4) / 256; i++) {
        int ch = tid + i * 256;
        int row = ch >> 2, c16 = ch & 3;
        cpa16(sA + row * ROWB + c16 * 16, A + (size_t)(arow0 + row) * g.K + off + c16 * 8);
    }
#pragma unroll
    for (int i = 0; i < 2; i++) {
        int ch = tid + i * 256;
        int row = ch >> 2, c16 = ch & 3;
        cpa16(sB + row * ROWB + c16 * 16, B + (size_t)(brow0 + row) * g.K + off + c16 * 8);
    }
}

// CTA tile (32*MT) x 128, 8 warps 2(M) x 4(N), warp tile (16*MT) x 32.
template<int MT>
__device__ __forceinline__ void gemm_main(
    uint32_t sbase, const GemmSrc& g, int NC, int arow0, int brow0,
    float (&acc)[MT][4][4])
{
    const int tid = threadIdx.x, lane = tid & 31, w = tid >> 5;
    const int wm = w & 1, wn = w >> 1;
    const int AROWS = 32 * MT;

#pragma unroll
    for (int i = 0; i < STAGES - 1; i++) {
        load_chunk<MT>(sbase, i, g, i, arow0, brow0, tid);
        CP_COMMIT();
    }

    const uint32_t aoff = (wm * (16 * MT) + (lane & 15)) * ROWB + (lane >> 4) * 16;
    const uint32_t boff = (wn * 32 + (lane & 15)) * ROWB + (lane >> 4) * 16;

    for (int c = 0; c < NC; c++) {
        CP_WAIT2();
        __syncthreads();
        if (c + STAGES - 1 < NC)
            load_chunk<MT>(sbase, (c + STAGES - 1) & (STAGES - 1), g, c + STAGES - 1,
                           arow0, brow0, tid);
        CP_COMMIT();

        uint32_t sA = sbase + (c & (STAGES - 1)) * STAGEB(MT);
        uint32_t sB = sA + AROWS * ROWB;
#pragma unroll
        for (int k16 = 0; k16 < 2; k16++) {
            uint32_t a[MT][4], b[2][4];
#pragma unroll
            for (int mt = 0; mt < MT; mt++)
                LDMX4(a[mt], sA + aoff + mt * 16 * ROWB + k16 * 32);
#pragma unroll
            for (int np = 0; np < 2; np++)
                LDMX4(b[np], sB + boff + np * 16 * ROWB + k16 * 32);
#pragma unroll
            for (int mt = 0; mt < MT; mt++)
#pragma unroll
                for (int nt = 0; nt < 4; nt++)
                    MMA16816(acc[mt][nt], a[mt], b[nt >> 1][nt & 1], b[nt >> 1][(nt & 1) + 2]);
        }
    }
    __syncthreads();
}

// ---------------- proj: h = relu(hs@W^T + b) -> h_hi (MT=2, 64x128 tiles) ----
__global__ __launch_bounds__(256) void proj_gemm_kernel(const float* __restrict__ bias)
{
    extern __shared__ char smem[];
    uint32_t sbase = smem_u32(smem);
    float acc[2][4][4] = {};

    GemmSrc g;
    g.ahi = g_hs_hi; g.alo = g_hs_lo; g.bhi = g_w_hi; g.blo = g_w_lo;
    g.K = D_; g.cpp = D_ / BK;

    const int row0 = blockIdx.y * 64, col0 = blockIdx.x * 128;
    gemm_main<2>(sbase, g, 3 * (D_ / BK), row0, col0, acc);

    const int lane = threadIdx.x & 31, w = threadIdx.x >> 5;
    const int wm = w & 1, wn = w >> 1;
    uint32_t* hhi = (uint32_t*)g_h_hi;

#pragma unroll
    for (int nt = 0; nt < 4; nt++) {
        int col = col0 + wn * 32 + nt * 8 + (lane & 3) * 2;
        float b0 = bias[col], b1 = bias[col + 1];
#pragma unroll
        for (int mt = 0; mt < 2; mt++) {
            int r0 = row0 + wm * 32 + mt * 16 + (lane >> 2);
#pragma unroll
            for (int hh = 0; hh < 2; hh++) {
                int r = r0 + hh * 8;
                float v0 = fmaxf(acc[mt][nt][hh * 2 + 0] + b0, 0.f);
                float v1 = fmaxf(acc[mt][nt][hh * 2 + 1] + b1, 0.f);
                __nv_bfloat16 h0 = __float2bfloat16(v0), h1 = __float2bfloat16(v1);
                uint32_t hp = (uint32_t)*(unsigned short*)&h0 | ((uint32_t)*(unsigned short*)&h1 << 16);
                hhi[((size_t)r * P_ + col) >> 1] = hp;
            }
        }
    }
}

// ---------------- scores: out = (h_hi@h_hi^T)*s + c (MT=4, tri+mirror) ----
__global__ __launch_bounds__(256) void scores_gemm_kernel(
    const float* __restrict__ clf_w, const float* __restrict__ clf_b,
    float* __restrict__ out)
{
    extern __shared__ char smem[];
    uint32_t sbase = smem_u32(smem);

    const int idx = blockIdx.x;
    int bi = (int)((sqrtf(8.f * (float)idx + 1.f) - 1.f) * 0.5f);
    while ((bi + 1) * (bi + 2) / 2 <= idx) bi++;
    while (bi * (bi + 1) / 2 > idx)       bi--;
    const int bj = idx - bi * (bi + 1) / 2;
    const int rows0 = bi * 128, cols0 = bj * 128;

    const size_t hoff = (size_t)blockIdx.z * S_ * P_;
    float* outb = out + (size_t)blockIdx.z * S_ * S_;

    float acc[4][4][4] = {};
    GemmSrc g;
    g.ahi = g_h_hi + hoff; g.alo = g_h_hi + hoff;   // single phase: p==0 always
    g.bhi = g_h_hi + hoff; g.blo = g_h_hi + hoff;
    g.K = P_; g.cpp = P_ / BK;
    gemm_main<4>(sbase, g, P_ / BK, rows0, cols0, acc);   // NC=8 (pure bf16)

    const float sw = clf_w[0], cb = clf_b[0];
    const int lane = threadIdx.x & 31, w = threadIdx.x >> 5;
    const int wm = w & 1, wn = w >> 1;
    float* sep = (float*)smem;   // [128][132] f32 = 67584 <= 81920

#pragma unroll
    for (int mt = 0; mt < 4; mt++)
#pragma unroll
        for (int nt = 0; nt < 4; nt++) {
            int lr = wm * 64 + mt * 16 + (lane >> 2);
            int lc = wn * 32 + nt * 8 + (lane & 3) * 2;
            sep[lr * 132 + lc]           = acc[mt][nt][0];
            sep[lr * 132 + lc + 1]       = acc[mt][nt][1];
            sep[(lr + 8) * 132 + lc]     = acc[mt][nt][2];
            sep[(lr + 8) * 132 + lc + 1] = acc[mt][nt][3];
        }
    __syncthreads();

    // direct block (coalesced rows)
#pragma unroll
    for (int pass = 0; pass < 16; pass++) {
        int r = pass * 8 + w;
        float4 v = *(const float4*)(sep + r * 132 + lane * 4);
        v.x = fmaf(v.x, sw, cb); v.y = fmaf(v.y, sw, cb);
        v.z = fmaf(v.z, sw, cb); v.w = fmaf(v.w, sw, cb);
        *(float4*)&outb[(size_t)(rows0 + r) * S_ + cols0 + lane * 4] = v;
    }
    // mirrored block
    if (bi != bj) {
#pragma unroll
        for (int pass = 0; pass < 16; pass++) {
            int c = pass * 8 + w;
            float4 v;
            v.x = fmaf(sep[(lane * 4 + 0) * 132 + c], sw, cb);
            v.y = fmaf(sep[(lane * 4 + 1) * 132 + c], sw, cb);
            v.z = fmaf(sep[(lane * 4 + 2) * 132 + c], sw, cb);
            v.w = fmaf(sep[(lane * 4 + 3) * 132 + c], sw, cb);
            *(float4*)&outb[(size_t)(cols0 + c) * S_ + rows0 + lane * 4] = v;
        }
    }
}

// ---------------- launch ----------------
extern "C" void kernel_launch(void* const* d_in, const int* in_sizes, int n_in,
                              void* d_out, int out_size)
{
    const float* hs     = (const float*)d_in[0];
    const float* proj_w = (const float*)d_in[1];
    const float* proj_b = (const float*)d_in[2];
    const float* clf_w  = (const float*)d_in[3];
    const float* clf_b  = (const float*)d_in[4];
    float* out = (float*)d_out;

    unsigned short *hs_hi, *hs_lo, *w_hi, *w_lo;
    cudaGetSymbolAddress((void**)&hs_hi, g_hs_hi);
    cudaGetSymbolAddress((void**)&hs_lo, g_hs_lo);
    cudaGetSymbolAddress((void**)&w_hi,  g_w_hi);
    cudaGetSymbolAddress((void**)&w_lo,  g_w_lo);

    cudaFuncSetAttribute(proj_gemm_kernel,
                         cudaFuncAttributeMaxDynamicSharedMemorySize, SMEMB(2));
    cudaFuncSetAttribute(scores_gemm_kernel,
                         cudaFuncAttributeMaxDynamicSharedMemorySize, SMEMB(4));

    {   // fp32 -> hi/lo bf16
        int n4 = (MROWS * D_) / 4;
        convert_kernel<<<(n4 + 255) / 256, 256>>>(hs, hs_hi, hs_lo, n4);
        int w4 = (P_ * D_) / 4;
        convert_kernel<<<(w4 + 255) / 256, 256>>>(proj_w, w_hi, w_lo, w4);
    }
    {   // projection (3-phase split) + relu -> h_hi: 64x128 tiles
        dim3 grid(P_ / 128, MROWS / 64);    // (2, 128) = 256 CTAs
        proj_gemm_kernel<<<grid, 256, SMEMB(2)>>>(proj_b);
    }
    {   // symmetric scores, pure bf16: 128x128 triangular tiles
        const int nt = S_ / 128;                 // 16
        dim3 grid(nt * (nt + 1) / 2, 1, B_);     // (136, 1, 4)
        scores_gemm_kernel<<<grid, 256, SMEMB(4)>>>(clf_w, clf_b, out);
    }
}

// round 7
// speedup vs baseline: 2.6320x; 1.5418x over previous
#include <cuda_runtime.h>
#include <cuda_fp16.h>
#include <math.h>
#include <cstdint>

// ContactMapHead via single-pass fp16 HMMA GEMMs (tcgen05 rejected by sm_103
// PTX target). fp16 has 11 mantissa bits; products are exact in the fp32
// accumulator, so no Markidis splitting is needed (error ~1e-4 << 1e-3 gate).
//   h      = relu(hs @ W^T + b)        hs:[8192,1024] W:[256,1024]
//   scores = (h @ h^T) * s + c         per batch of 4, S=2048 (triangular+mirror)

#define B_    4
#define S_    2048
#define D_    1024
#define P_    256
#define MROWS 8192

#define BK      32
#define STAGES  4
#define ROWB    80                         // 64 data bytes + 16 pad

#define STAGEB(MT)  ((32 * (MT) + 128) * ROWB)   // A rows + 128 B rows
#define SMEMB(MT)   (STAGES * STAGEB(MT))

// ---------------- scratch ----------------
__device__ unsigned short g_hs16[(size_t)MROWS * D_];
__device__ unsigned short g_w16[(size_t)P_ * D_];
__device__ unsigned short g_h16[(size_t)MROWS * P_];

// ---------------- asm helpers ----------------
__device__ __forceinline__ uint32_t smem_u32(const void* p) {
    uint32_t a;
    asm("{ .reg .u64 t; cvta.to.shared.u64 t, %1; cvt.u32.u64 %0, t; }" : "=r"(a) : "l"(p));
    return a;
}
__device__ __forceinline__ void cpa16(uint32_t s, const void* g) {
    asm volatile("cp.async.cg.shared.global [%0], [%1], 16;" :: "r"(s), "l"(g));
}
#define CP_COMMIT() asm volatile("cp.async.commit_group;" ::: "memory")
#define CP_WAIT2()  asm volatile("cp.async.wait_group 2;" ::: "memory")

#define LDMX4(r, addr) \
    asm volatile("ldmatrix.sync.aligned.m8n8.x4.shared.b16 {%0,%1,%2,%3}, [%4];" \
        : "=r"((r)[0]), "=r"((r)[1]), "=r"((r)[2]), "=r"((r)[3]) : "r"(addr))

#define MMA16816(d, a, b0, b1) \
    asm volatile("mma.sync.aligned.m16n8k16.row.col.f32.f16.f16.f32 " \
        "{%0,%1,%2,%3},{%4,%5,%6,%7},{%8,%9},{%0,%1,%2,%3};" \
        : "+f"((d)[0]), "+f"((d)[1]), "+f"((d)[2]), "+f"((d)[3]) \
        : "r"((a)[0]), "r"((a)[1]), "r"((a)[2]), "r"((a)[3]), "r"(b0), "r"(b1))

// ---------------- fp32 -> fp16 convert (hs then w, one launch) ----------------
__global__ __launch_bounds__(256) void convert_kernel(
    const float* __restrict__ hs, const float* __restrict__ w,
    unsigned short* __restrict__ hs16, unsigned short* __restrict__ w16,
    int n4_hs, int n4_total)
{
    int i = blockIdx.x * 256 + threadIdx.x;
    if (i >= n4_total) return;
    const float* src;
    unsigned short* dst;
    int j;
    if (i < n4_hs) { src = hs; dst = hs16; j = i; }
    else           { src = w;  dst = w16;  j = i - n4_hs; }
    float4 v = ((const float4*)src)[j];
    __half2 lo = __floats2half2_rn(v.x, v.y);
    __half2 hi = __floats2half2_rn(v.z, v.w);
    uint2 o;
    o.x = *(uint32_t*)&lo;
    o.y = *(uint32_t*)&hi;
    ((uint2*)dst)[j] = o;
}

// ---------------- GEMM machinery ----------------
struct GemmSrc {
    const unsigned short *a, *b;
    int K;
};

template<int MT>
__device__ __forceinline__ void load_chunk(
    uint32_t sbase, int slot, const GemmSrc& g, int koff,
    int arow0, int brow0, int tid)
{
    const int AROWS = 32 * MT;
    uint32_t sA = sbase + slot * STAGEB(MT);
    uint32_t sB = sA + AROWS * ROWB;
#pragma unroll
    for (int i = 0; i < (AROWS * 4) / 256; i++) {
        int ch = tid + i * 256;
        int row = ch >> 2, c16 = ch & 3;
        cpa16(sA + row * ROWB + c16 * 16, g.a + (size_t)(arow0 + row) * g.K + koff + c16 * 8);
    }
#pragma unroll
    for (int i = 0; i < 2; i++) {
        int ch = tid + i * 256;
        int row = ch >> 2, c16 = ch & 3;
        cpa16(sB + row * ROWB + c16 * 16, g.b + (size_t)(brow0 + row) * g.K + koff + c16 * 8);
    }
}

// CTA tile (32*MT) x 128, 8 warps 2(M) x 4(N), warp tile (16*MT) x 32.
template<int MT>
__device__ __forceinline__ void gemm_main(
    uint32_t sbase, const GemmSrc& g, int NC, int arow0, int brow0,
    float (&acc)[MT][4][4])
{
    const int tid = threadIdx.x, lane = tid & 31, w = tid >> 5;
    const int wm = w & 1, wn = w >> 1;
    const int AROWS = 32 * MT;

#pragma unroll
    for (int i = 0; i < STAGES - 1; i++) {
        load_chunk<MT>(sbase, i, g, i * BK, arow0, brow0, tid);
        CP_COMMIT();
    }

    const uint32_t aoff = (wm * (16 * MT) + (lane & 15)) * ROWB + (lane >> 4) * 16;
    const uint32_t boff = (wn * 32 + (lane & 15)) * ROWB + (lane >> 4) * 16;

    for (int c = 0; c < NC; c++) {
        CP_WAIT2();
        __syncthreads();
        if (c + STAGES - 1 < NC)
            load_chunk<MT>(sbase, (c + STAGES - 1) & (STAGES - 1), g,
                           (c + STAGES - 1) * BK, arow0, brow0, tid);
        CP_COMMIT();

        uint32_t sA = sbase + (c & (STAGES - 1)) * STAGEB(MT);
        uint32_t sB = sA + AROWS * ROWB;
#pragma unroll
        for (int k16 = 0; k16 < 2; k16++) {
            uint32_t a[MT][4], b[2][4];
#pragma unroll
            for (int mt = 0; mt < MT; mt++)
                LDMX4(a[mt], sA + aoff + mt * 16 * ROWB + k16 * 32);
#pragma unroll
            for (int np = 0; np < 2; np++)
                LDMX4(b[np], sB + boff + np * 16 * ROWB + k16 * 32);
#pragma unroll
            for (int mt = 0; mt < MT; mt++)
#pragma unroll
                for (int nt = 0; nt < 4; nt++)
                    MMA16816(acc[mt][nt], a[mt], b[nt >> 1][nt & 1], b[nt >> 1][(nt & 1) + 2]);
        }
    }
    __syncthreads();
}

// ---------------- proj: h = relu(hs@W^T + b) -> h fp16 (MT=2, 64x128) ----
__global__ __launch_bounds__(256) void proj_gemm_kernel(const float* __restrict__ bias)
{
    extern __shared__ char smem[];
    uint32_t sbase = smem_u32(smem);
    float acc[2][4][4] = {};

    GemmSrc g;
    g.a = g_hs16; g.b = g_w16; g.K = D_;

    const int row0 = blockIdx.y * 64, col0 = blockIdx.x * 128;
    gemm_main<2>(sbase, g, D_ / BK, row0, col0, acc);

    const int lane = threadIdx.x & 31, w = threadIdx.x >> 5;
    const int wm = w & 1, wn = w >> 1;
    uint32_t* hh = (uint32_t*)g_h16;

#pragma unroll
    for (int nt = 0; nt < 4; nt++) {
        int col = col0 + wn * 32 + nt * 8 + (lane & 3) * 2;
        float b0 = bias[col], b1 = bias[col + 1];
#pragma unroll
        for (int mt = 0; mt < 2; mt++) {
            int r0 = row0 + wm * 32 + mt * 16 + (lane >> 2);
#pragma unroll
            for (int hh2 = 0; hh2 < 2; hh2++) {
                int r = r0 + hh2 * 8;
                float v0 = fmaxf(acc[mt][nt][hh2 * 2 + 0] + b0, 0.f);
                float v1 = fmaxf(acc[mt][nt][hh2 * 2 + 1] + b1, 0.f);
                __half2 p = __floats2half2_rn(v0, v1);
                hh[((size_t)r * P_ + col) >> 1] = *(uint32_t*)&p;
            }
        }
    }
}

// ---------------- scores: out = (h@h^T)*s + c (MT=4, tri+mirror) ----
__global__ __launch_bounds__(256) void scores_gemm_kernel(
    const float* __restrict__ clf_w, const float* __restrict__ clf_b,
    float* __restrict__ out)
{
    extern __shared__ char smem[];
    uint32_t sbase = smem_u32(smem);

    const int idx = blockIdx.x;
    int bi = (int)((sqrtf(8.f * (float)idx + 1.f) - 1.f) * 0.5f);
    while ((bi + 1) * (bi + 2) / 2 <= idx) bi++;
    while (bi * (bi + 1) / 2 > idx)       bi--;
    const int bj = idx - bi * (bi + 1) / 2;
    const int rows0 = bi * 128, cols0 = bj * 128;

    const size_t hoff = (size_t)blockIdx.z * S_ * P_;
    float* outb = out + (size_t)blockIdx.z * S_ * S_;

    float acc[4][4][4] = {};
    GemmSrc g;
    g.a = g_h16 + hoff; g.b = g_h16 + hoff; g.K = P_;
    gemm_main<4>(sbase, g, P_ / BK, rows0, cols0, acc);   // NC=8

    const float sw = clf_w[0], cb = clf_b[0];
    const int lane = threadIdx.x & 31, w = threadIdx.x >> 5;
    const int wm = w & 1, wn = w >> 1;
    float* sep = (float*)smem;   // [128][132] f32 = 67584 <= 81920

#pragma unroll
    for (int mt = 0; mt < 4; mt++)
#pragma unroll
        for (int nt = 0; nt < 4; nt++) {
            int lr = wm * 64 + mt * 16 + (lane >> 2);
            int lc = wn * 32 + nt * 8 + (lane & 3) * 2;
            sep[lr * 132 + lc]           = acc[mt][nt][0];
            sep[lr * 132 + lc + 1]       = acc[mt][nt][1];
            sep[(lr + 8) * 132 + lc]     = acc[mt][nt][2];
            sep[(lr + 8) * 132 + lc + 1] = acc[mt][nt][3];
        }
    __syncthreads();

    // direct block (coalesced rows)
#pragma unroll
    for (int pass = 0; pass < 16; pass++) {
        int r = pass * 8 + w;
        float4 v = *(const float4*)(sep + r * 132 + lane * 4);
        v.x = fmaf(v.x, sw, cb); v.y = fmaf(v.y, sw, cb);
        v.z = fmaf(v.z, sw, cb); v.w = fmaf(v.w, sw, cb);
        *(float4*)&outb[(size_t)(rows0 + r) * S_ + cols0 + lane * 4] = v;
    }
    // mirrored block
    if (bi != bj) {
#pragma unroll
        for (int pass = 0; pass < 16; pass++) {
            int c = pass * 8 + w;
            float4 v;
            v.x = fmaf(sep[(lane * 4 + 0) * 132 + c], sw, cb);
            v.y = fmaf(sep[(lane * 4 + 1) * 132 + c], sw, cb);
            v.z = fmaf(sep[(lane * 4 + 2) * 132 + c], sw, cb);
            v.w = fmaf(sep[(lane * 4 + 3) * 132 + c], sw, cb);
            *(float4*)&outb[(size_t)(cols0 + c) * S_ + rows0 + lane * 4] = v;
        }
    }
}

// ---------------- launch ----------------
extern "C" void kernel_launch(void* const* d_in, const int* in_sizes, int n_in,
                              void* d_out, int out_size)
{
    const float* hs     = (const float*)d_in[0];
    const float* proj_w = (const float*)d_in[1];
    const float* proj_b = (const float*)d_in[2];
    const float* clf_w  = (const float*)d_in[3];
    const float* clf_b  = (const float*)d_in[4];
    float* out = (float*)d_out;

    unsigned short *hs16, *w16;
    cudaGetSymbolAddress((void**)&hs16, g_hs16);
    cudaGetSymbolAddress((void**)&w16,  g_w16);

    cudaFuncSetAttribute(proj_gemm_kernel,
                         cudaFuncAttributeMaxDynamicSharedMemorySize, SMEMB(2));
    cudaFuncSetAttribute(scores_gemm_kernel,
                         cudaFuncAttributeMaxDynamicSharedMemorySize, SMEMB(4));

    {   // fp32 -> fp16 (hs + w in one launch)
        int n4_hs = (MROWS * D_) / 4;
        int n4_t  = n4_hs + (P_ * D_) / 4;
        convert_kernel<<<(n4_t + 255) / 256, 256>>>(hs, proj_w, hs16, w16, n4_hs, n4_t);
    }
    {   // projection + relu -> h fp16: 64x128 tiles
        dim3 grid(P_ / 128, MROWS / 64);    // (2, 128) = 256 CTAs
        proj_gemm_kernel<<<grid, 256, SMEMB(2)>>>(proj_b);
    }
    {   // symmetric scores: 128x128 triangular tiles
        const int nt = S_ / 128;                 // 16
        dim3 grid(nt * (nt + 1) / 2, 1, B_);     // (136, 1, 4)
        scores_gemm_kernel<<<grid, 256, SMEMB(4)>>>(clf_w, clf_b, out);
    }
}

// round 8
// speedup vs baseline: 3.0173x; 1.1464x over previous
#include <cuda_runtime.h>
#include <cuda_fp16.h>
#include <math.h>
#include <cstdint>

// ContactMapHead via single-pass fp16 HMMA GEMMs (tcgen05 rejected by sm_103
// PTX target). fp16 products are exact in fp32 accum -> no splitting needed.
//   h      = relu(hs @ W^T + b)        hs:[8192,1024] W:[256,1024]
//   scores = (h @ h^T) * s + c         per batch of 4, S=2048
// R7: scores uses 64x128 tiles (MT=2) for 3 CTAs/SM occupancy; symmetric
// coverage via asymmetric-tile triangular enumeration + mirrored writes.

#define B_    4
#define S_    2048
#define D_    1024
#define P_    256
#define MROWS 8192

#define BK      32
#define STAGES  4
#define ROWB    80                         // 64 data bytes + 16 pad

#define STAGEB(MT)  ((32 * (MT) + 128) * ROWB)   // A rows + 128 B rows
#define SMEMB(MT)   (STAGES * STAGEB(MT))

// ---------------- scratch ----------------
__device__ unsigned short g_hs16[(size_t)MROWS * D_];
__device__ unsigned short g_w16[(size_t)P_ * D_];
__device__ unsigned short g_h16[(size_t)MROWS * P_];

// ---------------- asm helpers ----------------
__device__ __forceinline__ uint32_t smem_u32(const void* p) {
    uint32_t a;
    asm("{ .reg .u64 t; cvta.to.shared.u64 t, %1; cvt.u32.u64 %0, t; }" : "=r"(a) : "l"(p));
    return a;
}
__device__ __forceinline__ void cpa16(uint32_t s, const void* g) {
    asm volatile("cp.async.cg.shared.global [%0], [%1], 16;" :: "r"(s), "l"(g));
}
#define CP_COMMIT() asm volatile("cp.async.commit_group;" ::: "memory")
#define CP_WAIT2()  asm volatile("cp.async.wait_group 2;" ::: "memory")

#define LDMX4(r, addr) \
    asm volatile("ldmatrix.sync.aligned.m8n8.x4.shared.b16 {%0,%1,%2,%3}, [%4];" \
        : "=r"((r)[0]), "=r"((r)[1]), "=r"((r)[2]), "=r"((r)[3]) : "r"(addr))

#define MMA16816(d, a, b0, b1) \
    asm volatile("mma.sync.aligned.m16n8k16.row.col.f32.f16.f16.f32 " \
        "{%0,%1,%2,%3},{%4,%5,%6,%7},{%8,%9},{%0,%1,%2,%3};" \
        : "+f"((d)[0]), "+f"((d)[1]), "+f"((d)[2]), "+f"((d)[3]) \
        : "r"((a)[0]), "r"((a)[1]), "r"((a)[2]), "r"((a)[3]), "r"(b0), "r"(b1))

// ---------------- fp32 -> fp16 convert (hs then w, one launch) ----------------
__global__ __launch_bounds__(256) void convert_kernel(
    const float* __restrict__ hs, const float* __restrict__ w,
    unsigned short* __restrict__ hs16, unsigned short* __restrict__ w16,
    int n4_hs, int n4_total)
{
    int i = blockIdx.x * 256 + threadIdx.x;
    if (i >= n4_total) return;
    const float* src;
    unsigned short* dst;
    int j;
    if (i < n4_hs) { src = hs; dst = hs16; j = i; }
    else           { src = w;  dst = w16;  j = i - n4_hs; }
    float4 v = ((const float4*)src)[j];
    __half2 lo = __floats2half2_rn(v.x, v.y);
    __half2 hi = __floats2half2_rn(v.z, v.w);
    uint2 o;
    o.x = *(uint32_t*)&lo;
    o.y = *(uint32_t*)&hi;
    ((uint2*)dst)[j] = o;
}

// ---------------- GEMM machinery ----------------
struct GemmSrc {
    const unsigned short *a, *b;
    int K;
};

template<int MT>
__device__ __forceinline__ void load_chunk(
    uint32_t sbase, int slot, const GemmSrc& g, int koff,
    int arow0, int brow0, int tid)
{
    const int AROWS = 32 * MT;
    uint32_t sA = sbase + slot * STAGEB(MT);
    uint32_t sB = sA + AROWS * ROWB;
#pragma unroll
    for (int i = 0; i < (AROWS * 4) / 256; i++) {
        int ch = tid + i * 256;
        int row = ch >> 2, c16 = ch & 3;
        cpa16(sA + row * ROWB + c16 * 16, g.a + (size_t)(arow0 + row) * g.K + koff + c16 * 8);
    }
#pragma unroll
    for (int i = 0; i < 2; i++) {
        int ch = tid + i * 256;
        int row = ch >> 2, c16 = ch & 3;
        cpa16(sB + row * ROWB + c16 * 16, g.b + (size_t)(brow0 + row) * g.K + koff + c16 * 8);
    }
}

// CTA tile (32*MT) x 128, 8 warps 2(M) x 4(N), warp tile (16*MT) x 32.
template<int MT>
__device__ __forceinline__ void gemm_main(
    uint32_t sbase, const GemmSrc& g, int NC, int arow0, int brow0,
    float (&acc)[MT][4][4])
{
    const int tid = threadIdx.x, lane = tid & 31, w = tid >> 5;
    const int wm = w & 1, wn = w >> 1;
    const int AROWS = 32 * MT;

#pragma unroll
    for (int i = 0; i < STAGES - 1; i++) {
        load_chunk<MT>(sbase, i, g, i * BK, arow0, brow0, tid);
        CP_COMMIT();
    }

    const uint32_t aoff = (wm * (16 * MT) + (lane & 15)) * ROWB + (lane >> 4) * 16;
    const uint32_t boff = (wn * 32 + (lane & 15)) * ROWB + (lane >> 4) * 16;

    for (int c = 0; c < NC; c++) {
        CP_WAIT2();
        __syncthreads();
        if (c + STAGES - 1 < NC)
            load_chunk<MT>(sbase, (c + STAGES - 1) & (STAGES - 1), g,
                           (c + STAGES - 1) * BK, arow0, brow0, tid);
        CP_COMMIT();

        uint32_t sA = sbase + (c & (STAGES - 1)) * STAGEB(MT);
        uint32_t sB = sA + AROWS * ROWB;
#pragma unroll
        for (int k16 = 0; k16 < 2; k16++) {
            uint32_t a[MT][4], b[2][4];
#pragma unroll
            for (int mt = 0; mt < MT; mt++)
                LDMX4(a[mt], sA + aoff + mt * 16 * ROWB + k16 * 32);
#pragma unroll
            for (int np = 0; np < 2; np++)
                LDMX4(b[np], sB + boff + np * 16 * ROWB + k16 * 32);
#pragma unroll
            for (int mt = 0; mt < MT; mt++)
#pragma unroll
                for (int nt = 0; nt < 4; nt++)
                    MMA16816(acc[mt][nt], a[mt], b[nt >> 1][nt & 1], b[nt >> 1][(nt & 1) + 2]);
        }
    }
    __syncthreads();
}

// ---------------- proj: h = relu(hs@W^T + b) -> h fp16 (MT=2, 64x128) ----
__global__ __launch_bounds__(256) void proj_gemm_kernel(const float* __restrict__ bias)
{
    extern __shared__ char smem[];
    uint32_t sbase = smem_u32(smem);
    float acc[2][4][4] = {};

    GemmSrc g;
    g.a = g_hs16; g.b = g_w16; g.K = D_;

    const int row0 = blockIdx.y * 64, col0 = blockIdx.x * 128;
    gemm_main<2>(sbase, g, D_ / BK, row0, col0, acc);

    const int lane = threadIdx.x & 31, w = threadIdx.x >> 5;
    const int wm = w & 1, wn = w >> 1;
    uint32_t* hh = (uint32_t*)g_h16;

#pragma unroll
    for (int nt = 0; nt < 4; nt++) {
        int col = col0 + wn * 32 + nt * 8 + (lane & 3) * 2;
        float b0 = bias[col], b1 = bias[col + 1];
#pragma unroll
        for (int mt = 0; mt < 2; mt++) {
            int r0 = row0 + wm * 32 + mt * 16 + (lane >> 2);
#pragma unroll
            for (int hh2 = 0; hh2 < 2; hh2++) {
                int r = r0 + hh2 * 8;
                float v0 = fmaxf(acc[mt][nt][hh2 * 2 + 0] + b0, 0.f);
                float v1 = fmaxf(acc[mt][nt][hh2 * 2 + 1] + b1, 0.f);
                __half2 p = __floats2half2_rn(v0, v1);
                hh[((size_t)r * P_ + col) >> 1] = *(uint32_t*)&p;
            }
        }
    }
}

// ---------------- scores: 64x128 tiles, triangular asym enumeration ----------
// Per batch: col tiles j=0..15 (128 wide), row tiles i=2j..31 (64 tall).
// t = i - 2j; t<2 -> tile inside diagonal 128-block (direct write only;
// the two such tiles jointly cover the full diagonal block).
// t>=2 -> strictly lower: direct + mirrored (transpose) write.
__global__ __launch_bounds__(256) void scores_gemm_kernel(
    const float* __restrict__ clf_w, const float* __restrict__ clf_b,
    float* __restrict__ out)
{
    extern __shared__ char smem[];
    uint32_t sbase = smem_u32(smem);

    int t = blockIdx.x, j = 0;
    while (t >= 32 - 2 * j) { t -= 32 - 2 * j; j++; }
    const int i = 2 * j + t;
    const int rows0 = i * 64, cols0 = j * 128;
    const bool diag = (t < 2);

    const size_t hoff = (size_t)blockIdx.z * S_ * P_;
    float* outb = out + (size_t)blockIdx.z * S_ * S_;

    float acc[2][4][4] = {};
    GemmSrc g;
    g.a = g_h16 + hoff; g.b = g_h16 + hoff; g.K = P_;
    gemm_main<2>(sbase, g, P_ / BK, rows0, cols0, acc);   // NC=8

    const float sw = clf_w[0], cb = clf_b[0];
    const int lane = threadIdx.x & 31, w = threadIdx.x >> 5;
    const int wm = w & 1, wn = w >> 1;
    float* sep = (float*)smem;   // [64][132] f32 = 33792 <= SMEMB(2)

#pragma unroll
    for (int mt = 0; mt < 2; mt++)
#pragma unroll
        for (int nt = 0; nt < 4; nt++) {
            int lr = wm * 32 + mt * 16 + (lane >> 2);
            int lc = wn * 32 + nt * 8 + (lane & 3) * 2;
            sep[lr * 132 + lc]           = acc[mt][nt][0];
            sep[lr * 132 + lc + 1]       = acc[mt][nt][1];
            sep[(lr + 8) * 132 + lc]     = acc[mt][nt][2];
            sep[(lr + 8) * 132 + lc + 1] = acc[mt][nt][3];
        }
    __syncthreads();

    // direct block: 64 rows x 128 cols, coalesced
#pragma unroll
    for (int pass = 0; pass < 8; pass++) {
        int r = pass * 8 + w;
        float4 v = *(const float4*)(sep + r * 132 + lane * 4);
        v.x = fmaf(v.x, sw, cb); v.y = fmaf(v.y, sw, cb);
        v.z = fmaf(v.z, sw, cb); v.w = fmaf(v.w, sw, cb);
        *(float4*)&outb[(size_t)(rows0 + r) * S_ + cols0 + lane * 4] = v;
    }
    // mirrored block: 128 rows (cols0+c) x 64 cols (rows0+..)
    if (!diag) {
#pragma unroll
        for (int pass = 0; pass < 8; pass++) {
            int c  = pass * 16 + w * 2 + (lane >> 4);
            int rg = lane & 15;
            float4 v;
            v.x = fmaf(sep[(rg * 4 + 0) * 132 + c], sw, cb);
            v.y = fmaf(sep[(rg * 4 + 1) * 132 + c], sw, cb);
            v.z = fmaf(sep[(rg * 4 + 2) * 132 + c], sw, cb);
            v.w = fmaf(sep[(rg * 4 + 3) * 132 + c], sw, cb);
            *(float4*)&outb[(size_t)(cols0 + c) * S_ + rows0 + rg * 4] = v;
        }
    }
}

// ---------------- launch ----------------
extern "C" void kernel_launch(void* const* d_in, const int* in_sizes, int n_in,
                              void* d_out, int out_size)
{
    const float* hs     = (const float*)d_in[0];
    const float* proj_w = (const float*)d_in[1];
    const float* proj_b = (const float*)d_in[2];
    const float* clf_w  = (const float*)d_in[3];
    const float* clf_b  = (const float*)d_in[4];
    float* out = (float*)d_out;

    unsigned short *hs16, *w16;
    cudaGetSymbolAddress((void**)&hs16, g_hs16);
    cudaGetSymbolAddress((void**)&w16,  g_w16);

    cudaFuncSetAttribute(proj_gemm_kernel,
                         cudaFuncAttributeMaxDynamicSharedMemorySize, SMEMB(2));
    cudaFuncSetAttribute(scores_gemm_kernel,
                         cudaFuncAttributeMaxDynamicSharedMemorySize, SMEMB(2));

    {   // fp32 -> fp16 (hs + w in one launch)
        int n4_hs = (MROWS * D_) / 4;
        int n4_t  = n4_hs + (P_ * D_) / 4;
        convert_kernel<<<(n4_t + 255) / 256, 256>>>(hs, proj_w, hs16, w16, n4_hs, n4_t);
    }
    {   // projection + relu -> h fp16: 64x128 tiles
        dim3 grid(P_ / 128, MROWS / 64);    // (2, 128) = 256 CTAs
        proj_gemm_kernel<<<grid, 256, SMEMB(2)>>>(proj_b);
    }
    {   // symmetric scores: 64x128 tiles, 272 per batch
        dim3 grid(272, 1, B_);              // (272, 1, 4) = 1088 CTAs
        scores_gemm_kernel<<<grid, 256, SMEMB(2)>>>(clf_w, clf_b, out);
    }
}

// round 9
// speedup vs baseline: 3.1855x; 1.0557x over previous
#include <cuda_runtime.h>
#include <cuda_fp16.h>
#include <math.h>
#include <cstdint>

// ContactMapHead via single-pass fp16 HMMA GEMMs (tcgen05 rejected by sm_103
// PTX target). fp16 products are exact in the fp32 accumulator.
//   h      = relu(hs @ W^T + b)        hs:[8192,1024] W:[256,1024]
//   scores = (h @ h^T) * s + c         per batch of 4, S=2048
// R8: hs fp32->fp16 conversion fused into proj's A-load path (kills the big
// convert pass); scores moves to BK=64 2-stage pipeline (NC=4).

#define B_    4
#define S_    2048
#define D_    1024
#define P_    256
#define MROWS 8192

#define BK    32

// ---- proj smem layout: B 4-stage (ROWB=80) + A 2-slot fp16 staging ----
#define PROJ_ROWB   80
#define PROJ_BSTAGE (128 * PROJ_ROWB)         // 10240
#define PROJ_AOFF   (4 * PROJ_BSTAGE)         // 40960
#define PROJ_ASLOT  (64 * PROJ_ROWB)          // 5120
#define PROJ_SMEM   (PROJ_AOFF + 2 * PROJ_ASLOT)   // 51200

// ---- scores smem layout: BK=64, 2 stages, ROWB=144 ----
#define SC_ROWB    144
#define SC_ASIZE   (64 * SC_ROWB)             // 9216
#define SC_STAGE   ((64 + 128) * SC_ROWB)     // 27648
#define SC_SMEM    (2 * SC_STAGE)             // 55296 (epi 64*132*4=33792 fits)

// ---------------- scratch ----------------
__device__ unsigned short g_w16[(size_t)P_ * D_];
__device__ unsigned short g_h16[(size_t)MROWS * P_];

// ---------------- asm helpers ----------------
__device__ __forceinline__ uint32_t smem_u32(const void* p) {
    uint32_t a;
    asm("{ .reg .u64 t; cvta.to.shared.u64 t, %1; cvt.u32.u64 %0, t; }" : "=r"(a) : "l"(p));
    return a;
}
__device__ __forceinline__ void cpa16(uint32_t s, const void* g) {
    asm volatile("cp.async.cg.shared.global [%0], [%1], 16;" :: "r"(s), "l"(g));
}
#define CP_COMMIT() asm volatile("cp.async.commit_group;" ::: "memory")
#define CP_WAIT2()  asm volatile("cp.async.wait_group 2;" ::: "memory")
#define CP_WAIT1()  asm volatile("cp.async.wait_group 1;" ::: "memory")
#define CP_WAIT0()  asm volatile("cp.async.wait_group 0;" ::: "memory")

#define LDMX4(r, addr) \
    asm volatile("ldmatrix.sync.aligned.m8n8.x4.shared.b16 {%0,%1,%2,%3}, [%4];" \
        : "=r"((r)[0]), "=r"((r)[1]), "=r"((r)[2]), "=r"((r)[3]) : "r"(addr))

#define MMA16816(d, a, b0, b1) \
    asm volatile("mma.sync.aligned.m16n8k16.row.col.f32.f16.f16.f32 " \
        "{%0,%1,%2,%3},{%4,%5,%6,%7},{%8,%9},{%0,%1,%2,%3};" \
        : "+f"((d)[0]), "+f"((d)[1]), "+f"((d)[2]), "+f"((d)[3]) \
        : "r"((a)[0]), "r"((a)[1]), "r"((a)[2]), "r"((a)[3]), "r"(b0), "r"(b1))

#define STS128(addr, v) \
    asm volatile("st.shared.v4.b32 [%0], {%1,%2,%3,%4};" \
        :: "r"(addr), "r"((v).x), "r"((v).y), "r"((v).z), "r"((v).w))

// ---------------- fp32 -> fp16 convert for W only (0.5 MB) ----------------
__global__ __launch_bounds__(256) void convert_w_kernel(
    const float* __restrict__ w, unsigned short* __restrict__ w16)
{
    int i = blockIdx.x * 256 + threadIdx.x;           // (P_*D_)/4 elems
    float4 v = ((const float4*)w)[i];
    __half2 lo = __floats2half2_rn(v.x, v.y);
    __half2 hi = __floats2half2_rn(v.z, v.w);
    uint2 o;
    o.x = *(uint32_t*)&lo;
    o.y = *(uint32_t*)&hi;
    ((uint2*)w16)[i] = o;
}

// ---------------- proj: h = relu(hs@W^T + b) -> h fp16, fused convert -------
// 64x128 tile, 8 warps 2(M)x4(N). A: LDG fp32 -> cvt -> STS (2-slot double
// buffer, register prefetch). B: w16 cp.async 4-stage.
__global__ __launch_bounds__(256) void proj_gemm_kernel(
    const float* __restrict__ hs, const float* __restrict__ bias)
{
    extern __shared__ char smem[];
    uint32_t sbase = smem_u32(smem);
    const int tid = threadIdx.x, lane = tid & 31, w = tid >> 5;
    const int wm = w & 1, wn = w >> 1;
    const int row0 = blockIdx.y * 64, col0 = blockIdx.x * 128;
    const int NC = D_ / BK;   // 32

    // A addressing (per-thread: one 32-elem row segment = 2 float4)
    const float* aptr = hs + (size_t)(row0 + (tid >> 2)) * D_ + (tid & 3) * 8;
    const uint32_t asts = sbase + PROJ_AOFF + (tid >> 2) * PROJ_ROWB + (tid & 3) * 16;

    // prologue: B stages 0..2
#pragma unroll
    for (int i = 0; i < 3; i++) {
        uint32_t sB = sbase + i * PROJ_BSTAGE;
#pragma unroll
        for (int q = 0; q < 2; q++) {
            int ch = tid + q * 256;
            int r = ch >> 2, c16 = ch & 3;
            cpa16(sB + r * PROJ_ROWB + c16 * 16,
                  g_w16 + (size_t)(col0 + r) * D_ + i * BK + c16 * 8);
        }
        CP_COMMIT();
    }
    float4 ax = ((const float4*)aptr)[0];
    float4 ay = ((const float4*)aptr)[1];

    float acc[2][4][4] = {};
    const uint32_t aoffm = (wm * 32 + (lane & 15)) * PROJ_ROWB + (lane >> 4) * 16;
    const uint32_t boff  = (wn * 32 + (lane & 15)) * PROJ_ROWB + (lane >> 4) * 16;

    for (int c = 0; c < NC; c++) {
        float4 nx, ny;
        if (c + 1 < NC) {                      // prefetch next A chunk
            const float4* p = (const float4*)(aptr + (c + 1) * BK);
            nx = p[0]; ny = p[1];
        }
        __syncthreads();                       // prior compute done: A slot free
        {                                      // cvt + STS current A chunk
            __half2 h0 = __floats2half2_rn(ax.x, ax.y);
            __half2 h1 = __floats2half2_rn(ax.z, ax.w);
            __half2 h2 = __floats2half2_rn(ay.x, ay.y);
            __half2 h3 = __floats2half2_rn(ay.z, ay.w);
            uint4 v = { *(uint32_t*)&h0, *(uint32_t*)&h1,
                        *(uint32_t*)&h2, *(uint32_t*)&h3 };
            STS128(asts + (c & 1) * PROJ_ASLOT, v);
        }
        CP_WAIT2();                            // B stage c complete
        __syncthreads();                       // A stores + B visible
        if (c + 3 < NC) {                      // issue B stage c+3
            uint32_t sB = sbase + ((c + 3) & 3) * PROJ_BSTAGE;
#pragma unroll
            for (int q = 0; q < 2; q++) {
                int ch = tid + q * 256;
                int r = ch >> 2, c16 = ch & 3;
                cpa16(sB + r * PROJ_ROWB + c16 * 16,
                      g_w16 + (size_t)(col0 + r) * D_ + (c + 3) * BK + c16 * 8);
            }
        }
        CP_COMMIT();

        uint32_t sA = sbase + PROJ_AOFF + (c & 1) * PROJ_ASLOT;
        uint32_t sB = sbase + (c & 3) * PROJ_BSTAGE;
#pragma unroll
        for (int k16 = 0; k16 < 2; k16++) {
            uint32_t a[2][4], b[2][4];
#pragma unroll
            for (int mt = 0; mt < 2; mt++)
                LDMX4(a[mt], sA + aoffm + mt * 16 * PROJ_ROWB + k16 * 32);
#pragma unroll
            for (int np = 0; np < 2; np++)
                LDMX4(b[np], sB + boff + np * 16 * PROJ_ROWB + k16 * 32);
#pragma unroll
            for (int mt = 0; mt < 2; mt++)
#pragma unroll
                for (int nt = 0; nt < 4; nt++)
                    MMA16816(acc[mt][nt], a[mt], b[nt >> 1][nt & 1], b[nt >> 1][(nt & 1) + 2]);
        }
        ax = nx; ay = ny;
    }

    // epilogue: bias + relu -> h fp16 (direct, coalesced pairs)
    uint32_t* hh = (uint32_t*)g_h16;
#pragma unroll
    for (int nt = 0; nt < 4; nt++) {
        int col = col0 + wn * 32 + nt * 8 + (lane & 3) * 2;
        float b0 = bias[col], b1 = bias[col + 1];
#pragma unroll
        for (int mt = 0; mt < 2; mt++) {
            int r0 = row0 + wm * 32 + mt * 16 + (lane >> 2);
#pragma unroll
            for (int hh2 = 0; hh2 < 2; hh2++) {
                int r = r0 + hh2 * 8;
                float v0 = fmaxf(acc[mt][nt][hh2 * 2 + 0] + b0, 0.f);
                float v1 = fmaxf(acc[mt][nt][hh2 * 2 + 1] + b1, 0.f);
                __half2 p = __floats2half2_rn(v0, v1);
                hh[((size_t)r * P_ + col) >> 1] = *(uint32_t*)&p;
            }
        }
    }
}

// ---------------- scores: 64x128 tiles, BK=64, 2-stage, tri+mirror ----------
// Per batch: col tiles j=0..15 (128 wide), row tiles i=2j..31 (64 tall).
// t = i-2j; t<2 -> inside diagonal 128-block (direct only); t>=2 -> + mirror.
__global__ __launch_bounds__(256) void scores_gemm_kernel(
    const float* __restrict__ clf_w, const float* __restrict__ clf_b,
    float* __restrict__ out)
{
    extern __shared__ char smem[];
    uint32_t sbase = smem_u32(smem);
    const int tid = threadIdx.x, lane = tid & 31, w = tid >> 5;
    const int wm = w & 1, wn = w >> 1;

    int t = blockIdx.x, j = 0;
    while (t >= 32 - 2 * j) { t -= 32 - 2 * j; j++; }
    const int i = 2 * j + t;
    const int rows0 = i * 64, cols0 = j * 128;
    const bool diag = (t < 2);

    const unsigned short* hb = g_h16 + (size_t)blockIdx.z * S_ * P_;
    float* outb = out + (size_t)blockIdx.z * S_ * S_;

    // chunk loader: 64 A rows + 128 B rows, 64 fp16 elems (128B) per row
    auto load_chunk = [&](int slot, int koff) {
        uint32_t sA = sbase + slot * SC_STAGE;
        uint32_t sB = sA + SC_ASIZE;
#pragma unroll
        for (int q = 0; q < 2; q++) {
            int ch = tid + q * 256;
            int r = ch >> 3, c16 = ch & 7;
            cpa16(sA + r * SC_ROWB + c16 * 16,
                  hb + (size_t)(rows0 + r) * P_ + koff + c16 * 8);
        }
#pragma unroll
        for (int q = 0; q < 4; q++) {
            int ch = tid + q * 256;
            int r = ch >> 3, c16 = ch & 7;
            cpa16(sB + r * SC_ROWB + c16 * 16,
                  hb + (size_t)(cols0 + r) * P_ + koff + c16 * 8);
        }
    };

    load_chunk(0, 0);
    CP_COMMIT();

    float acc[2][4][4] = {};
    const uint32_t aoffm = (wm * 32 + (lane & 15)) * SC_ROWB + (lane >> 4) * 16;
    const uint32_t boff  = (wn * 32 + (lane & 15)) * SC_ROWB + (lane >> 4) * 16;
    const int NC = P_ / 64;   // 4

    for (int c = 0; c < NC; c++) {
        if (c + 1 < NC) {
            load_chunk((c + 1) & 1, (c + 1) * 64);
            CP_COMMIT();
            CP_WAIT1();
        } else {
            CP_WAIT0();
        }
        __syncthreads();

        uint32_t sA = sbase + (c & 1) * SC_STAGE;
        uint32_t sB = sA + SC_ASIZE;
#pragma unroll
        for (int k16 = 0; k16 < 4; k16++) {
            uint32_t a[2][4], b[2][4];
#pragma unroll
            for (int mt = 0; mt < 2; mt++)
                LDMX4(a[mt], sA + aoffm + mt * 16 * SC_ROWB + k16 * 32);
#pragma unroll
            for (int np = 0; np < 2; np++)
                LDMX4(b[np], sB + boff + np * 16 * SC_ROWB + k16 * 32);
#pragma unroll
            for (int mt = 0; mt < 2; mt++)
#pragma unroll
                for (int nt = 0; nt < 4; nt++)
                    MMA16816(acc[mt][nt], a[mt], b[nt >> 1][nt & 1], b[nt >> 1][(nt & 1) + 2]);
        }
        __syncthreads();
    }

    const float sw = clf_w[0], cb = clf_b[0];
    float* sep = (float*)smem;   // [64][132]

#pragma unroll
    for (int mt = 0; mt < 2; mt++)
#pragma unroll
        for (int nt = 0; nt < 4; nt++) {
            int lr = wm * 32 + mt * 16 + (lane >> 2);
            int lc = wn * 32 + nt * 8 + (lane & 3) * 2;
            sep[lr * 132 + lc]           = acc[mt][nt][0];
            sep[lr * 132 + lc + 1]       = acc[mt][nt][1];
            sep[(lr + 8) * 132 + lc]     = acc[mt][nt][2];
            sep[(lr + 8) * 132 + lc + 1] = acc[mt][nt][3];
        }
    __syncthreads();

    // direct block: 64 rows x 128 cols
#pragma unroll
    for (int pass = 0; pass < 8; pass++) {
        int r = pass * 8 + w;
        float4 v = *(const float4*)(sep + r * 132 + lane * 4);
        v.x = fmaf(v.x, sw, cb); v.y = fmaf(v.y, sw, cb);
        v.z = fmaf(v.z, sw, cb); v.w = fmaf(v.w, sw, cb);
        *(float4*)&outb[(size_t)(rows0 + r) * S_ + cols0 + lane * 4] = v;
    }
    // mirrored block: 128 rows x 64 cols
    if (!diag) {
#pragma unroll
        for (int pass = 0; pass < 8; pass++) {
            int c  = pass * 16 + w * 2 + (lane >> 4);
            int rg = lane & 15;
            float4 v;
            v.x = fmaf(sep[(rg * 4 + 0) * 132 + c], sw, cb);
            v.y = fmaf(sep[(rg * 4 + 1) * 132 + c], sw, cb);
            v.z = fmaf(sep[(rg * 4 + 2) * 132 + c], sw, cb);
            v.w = fmaf(sep[(rg * 4 + 3) * 132 + c], sw, cb);
            *(float4*)&outb[(size_t)(cols0 + c) * S_ + rows0 + rg * 4] = v;
        }
    }
}

// ---------------- launch ----------------
extern "C" void kernel_launch(void* const* d_in, const int* in_sizes, int n_in,
                              void* d_out, int out_size)
{
    const float* hs     = (const float*)d_in[0];
    const float* proj_w = (const float*)d_in[1];
    const float* proj_b = (const float*)d_in[2];
    const float* clf_w  = (const float*)d_in[3];
    const float* clf_b  = (const float*)d_in[4];
    float* out = (float*)d_out;

    unsigned short* w16;
    cudaGetSymbolAddress((void**)&w16, g_w16);

    cudaFuncSetAttribute(proj_gemm_kernel,
                         cudaFuncAttributeMaxDynamicSharedMemorySize, PROJ_SMEM);
    cudaFuncSetAttribute(scores_gemm_kernel,
                         cudaFuncAttributeMaxDynamicSharedMemorySize, SC_SMEM);

    {   // W fp32 -> fp16 only (hs conversion fused into proj)
        convert_w_kernel<<<(P_ * D_ / 4) / 256, 256>>>(proj_w, w16);
    }
    {   // projection + relu -> h fp16: 64x128 tiles, fused hs convert
        dim3 grid(P_ / 128, MROWS / 64);    // (2, 128) = 256 CTAs
        proj_gemm_kernel<<<grid, 256, PROJ_SMEM>>>(hs, proj_b);
    }
    {   // symmetric scores: 64x128 tiles, BK=64, 272 tiles/batch
        dim3 grid(272, 1, B_);              // 1088 CTAs
        scores_gemm_kernel<<<grid, 256, SC_SMEM>>>(clf_w, clf_b, out);
    }
}